// round 13
// baseline (speedup 1.0000x reference)
#include <cuda_runtime.h>
#include <cuda_fp16.h>
#include <mma.h>
#include <cstdint>
#include <math_constants.h>

using namespace nvcuda;

#define N_NODES 100000
#define E_EDGES 1600000
#define IN_F    128
#define OUT_F   32
#define HEADS   6
#define HC      (HEADS * OUT_F)   // 192
#define NEG_SLOPE 0.2f
#define SCAN_B  1024
#define NB      ((N_NODES + SCAN_B - 1) / SCAN_B)   // 98

#define PR 64
#define PTILES ((N_NODES + PR - 1) / PR)   // 1563
#define PROJ_GRID 296
// dynamic smem: ws[128][200] halves (25600) + cs[64][200] halves (12800)
#define WS_HALVES 25600
#define SMEM_BYTES ((WS_HALVES + 64 * 200) * 2)   // 76800

// ---------------- scratch (device globals; no allocation allowed) ----------
__device__ __half g_xp_h[N_NODES * HC];    // projected features [N,H,C] (fp16)
__device__ float  g_as [N_NODES * HEADS];
__device__ float  g_ad [N_NODES * HEADS];
__device__ int    g_csr[E_EDGES];
__device__ int    g_deg[N_NODES];          // zero at load; re-zeroed by k_agg each run
__device__ int    g_row[N_NODES];
__device__ int    g_cur[N_NODES];
__device__ int    g_scan[NB * SCAN_B];
__device__ int    g_bsum[NB];

// ---------------- helpers ---------------------------------------------------
__device__ __forceinline__ float selu_f(float x) {
    const float scale = 1.0507009873554805f;
    const float alpha = 1.6732632423543772f;
    return x > 0.0f ? scale * x : scale * alpha * (expf(x) - 1.0f);
}

// Per-block edge-dtype detect: random int32 pairs read as int64 are >= 2^32.
__device__ __forceinline__ int detect_is64(const void* ei) {
    const long long* p = (const long long*)ei;
    int ok = 1;
#pragma unroll
    for (int i = 0; i < 16; i++) {
        long long v = p[i];
        if (v < 0 || v >= (long long)N_NODES) { ok = 0; break; }
    }
    return ok;
}

// ---------------- degree histogram (reads dst half of ei only) ---------------
__global__ void k_hist(const void* __restrict__ ei) {
    __shared__ int s_is64;
    if (threadIdx.x == 0) s_is64 = detect_is64(ei);
    __syncthreads();
    int i = blockIdx.x * blockDim.x + threadIdx.x;
    if (i >= E_EDGES) return;
    int d;
    if (s_is64) d = (int)((const long long*)ei)[E_EDGES + i];
    else        d = ((const int*)ei)[E_EDGES + i];
    atomicAdd(&g_deg[d], 1);
}

// ---------------- projection GEMM: W persistent in smem ----------------------
// 296 blocks (2/SM), each grid-strides over 64-row tiles. W (fp16, 48KB+pad)
// loaded once per block; per tile only the x load + 48 MMAs + epilogue.
__global__ __launch_bounds__(256, 2) void k_proj(const float* __restrict__ x,
                                                 const float* __restrict__ W,
                                                 const float* __restrict__ att_src,
                                                 const float* __restrict__ att_dst) {
    extern __shared__ __half dsm[];
    __half (*ws)[200] = (__half(*)[200])dsm;                 // [128][200]
    __half (*cs)[200] = (__half(*)[200])(dsm + WS_HALVES);   // [64][200] x-tile / C-tile

    const int t    = threadIdx.x;
    const int w    = t >> 5;
    const int lane = t & 31;
    const int rt   = w & 3;      // row tile (16 rows)
    const int ch   = w >> 2;     // col half (96 cols)

    // load entire W fp32 -> fp16 smem once (128 x 192 = 12288 float2)
#pragma unroll
    for (int q = 0; q < (IN_F * HC / 2) / 256; q++) {  // 48 iters
        int i  = t + 256 * q;
        int kk = i / 96;
        int c2 = i - kk * 96;
        float2 f2 = ((const float2*)W)[(size_t)kk * 96 + c2];
        ((__half2*)&ws[kk][0])[c2] = __floats2half2_rn(f2.x, f2.y);
    }

    float aS[6], aD[6];
#pragma unroll
    for (int g = 0; g < 6; g++) {
        aS[g] = att_src[g * OUT_F + lane];
        aD[g] = att_dst[g * OUT_F + lane];
    }

    for (int tile = blockIdx.x; tile < PTILES; tile += gridDim.x) {
        const int row0 = tile * PR;
        __syncthreads();   // previous tile's cs reads done (also covers W load on iter 0)

        // load x tile -> fp16 smem (float2 -> half2), zero-pad OOB rows
#pragma unroll
        for (int q = 0; q < (PR * IN_F / 2) / 256; q++) {   // 16 iters
            int i  = t + 256 * q;
            int r  = i >> 6;            // 64 half2 per row
            int k2 = i & 63;
            int row = row0 + r;
            float2 f2 = (row < N_NODES) ? ((const float2*)x)[(size_t)row * 64 + k2]
                                        : make_float2(0.0f, 0.0f);
            ((__half2*)&cs[r][0])[k2] = __floats2half2_rn(f2.x, f2.y);
        }
        __syncthreads();

        wmma::fragment<wmma::accumulator, 16, 16, 16, float> acc[6];
#pragma unroll
        for (int j = 0; j < 6; j++) wmma::fill_fragment(acc[j], 0.0f);

#pragma unroll
        for (int ks = 0; ks < 8; ks++) {
            wmma::fragment<wmma::matrix_a, 16, 16, 16, __half, wmma::row_major> af;
            wmma::load_matrix_sync(af, &cs[rt * 16][ks * 16], 200);
#pragma unroll
            for (int j = 0; j < 6; j++) {
                wmma::fragment<wmma::matrix_b, 16, 16, 16, __half, wmma::row_major> bf;
                wmma::load_matrix_sync(bf, &ws[ks * 16][ch * 96 + j * 16], 200);
                wmma::mma_sync(acc[j], af, bf, acc[j]);
            }
        }

        __syncthreads();   // all x reads done before overwriting cs with C
#pragma unroll
        for (int j = 0; j < 6; j++) {
            wmma::fragment<wmma::accumulator, 16, 16, 16, __half> hf;
#pragma unroll
            for (int i = 0; i < hf.num_elements; i++) hf.x[i] = __float2half(acc[j].x[i]);
            wmma::store_matrix_sync(&cs[rt * 16][ch * 96 + j * 16], hf, 200, wmma::mem_row_major);
        }
        __syncthreads();

        // xp copy to global (uint4 = 8 halfs), coalesced
#pragma unroll
        for (int q = 0; q < (PR * HC / 8) / 256; q++) {   // 6 iters
            int i  = t + 256 * q;
            int r  = i / 24;
            int q8 = i - r * 24;
            int row = row0 + r;
            if (row < N_NODES) {
                uint4 v = *(const uint4*)&cs[r][q8 * 8];
                ((uint4*)&g_xp_h[(size_t)row * HC])[q8] = v;
            }
        }

        // attention halves: warp w handles rows w*8 .. w*8+7
#pragma unroll
        for (int p = 0; p < 8; p++) {
            const int ri  = w * 8 + p;
            const int row = row0 + ri;
            if (row >= N_NODES) break;
#pragma unroll
            for (int g = 0; g < 6; g++) {
                float v = __half2float(cs[ri][g * OUT_F + lane]);
                float vs = v * aS[g];
                float vd = v * aD[g];
#pragma unroll
                for (int off = 16; off > 0; off >>= 1) {
                    vs += __shfl_down_sync(0xffffffffu, vs, off);
                    vd += __shfl_down_sync(0xffffffffu, vd, off);
                }
                if (lane == 0) {
                    g_as[row * HEADS + g] = vs;
                    g_ad[row * HEADS + g] = vd;
                }
            }
        }
    }
}

// ---------------- scan (warp-shuffle version) --------------------------------
__global__ void k_scan1() {
    __shared__ int wsum[32];
    const int t = threadIdx.x, lane = t & 31, wid = t >> 5;
    const int i = blockIdx.x * SCAN_B + t;
    int v = (i < N_NODES) ? g_deg[i] : 0;
    int xv = v;
#pragma unroll
    for (int off = 1; off < 32; off <<= 1) {
        int y = __shfl_up_sync(0xffffffffu, xv, off);
        if (lane >= off) xv += y;
    }
    if (lane == 31) wsum[wid] = xv;
    __syncthreads();
    if (wid == 0) {
        int wv = wsum[lane];
#pragma unroll
        for (int off = 1; off < 32; off <<= 1) {
            int y = __shfl_up_sync(0xffffffffu, wv, off);
            if (lane >= off) wv += y;
        }
        wsum[lane] = wv;
    }
    __syncthreads();
    int incl = xv + (wid > 0 ? wsum[wid - 1] : 0);
    g_scan[blockIdx.x * SCAN_B + t] = incl;
    if (t == SCAN_B - 1) g_bsum[blockIdx.x] = incl;
}

__global__ void k_scan23() {
    __shared__ int sb[NB];
    int t = threadIdx.x;
    if (t < NB) sb[t] = g_bsum[t];
    __syncthreads();
    if (t == 0) {
        int run = 0;
        for (int b = 0; b < NB; b++) { int v = sb[b]; sb[b] = run; run += v; }
    }
    __syncthreads();
    int i = blockIdx.x * blockDim.x + t;
    if (i >= N_NODES) return;
    int rs = g_scan[i] - g_deg[i] + sb[i / SCAN_B];
    g_row[i] = rs;
    g_cur[i] = rs;
}

// ---------------- scatter: reads edge_index directly -------------------------
__global__ void k_scatter(const void* __restrict__ ei) {
    __shared__ int s_is64;
    if (threadIdx.x == 0) s_is64 = detect_is64(ei);
    __syncthreads();
    int i = blockIdx.x * blockDim.x + threadIdx.x;
    if (i >= E_EDGES) return;
    int s, d;
    if (s_is64) {
        const long long* p = (const long long*)ei;
        s = (int)p[i];
        d = (int)p[E_EDGES + i];
    } else {
        const int* p = (const int*)ei;
        s = p[i];
        d = p[E_EDGES + i];
    }
    int pos = atomicAdd(&g_cur[d], 1);
    g_csr[pos] = s;
}

// ---------------- fused softmax + aggregation + finalize ---------------------
// One warp per dst. half2 lane remap: lanes 0-15 even heads / 16-31 odd heads.
// Also re-zeroes g_deg[d] for the next invocation (self-cleaning invariant).
__global__ __launch_bounds__(256) void k_agg(const float* __restrict__ bias,
                                             float* __restrict__ out) {
    const int d    = (blockIdx.x * blockDim.x + threadIdx.x) >> 5;
    const int lane = threadIdx.x & 31;
    if (d >= N_NODES) return;

    const int base = g_row[d];
    const int deg  = g_deg[d];
    if (lane == 0) g_deg[d] = 0;         // restore invariant for next run
    const int hsel = lane >> 4;          // 0: even heads, 1: odd heads

    float ad_l = 0.0f;
    if (lane < HEADS) ad_l = g_ad[d * HEADS + lane];

    float2 A0 = {0, 0}, A1 = {0, 0}, A2 = {0, 0};
    float s = 0.0f;

    for (int j0 = 0; j0 < deg; j0 += 32) {
        const int nv = min(32, deg - j0);
        int mysrc = 0;
        if (lane < nv) mysrc = g_csr[base + j0 + lane];

        int j = 0;
        for (; j + 1 < nv; j += 2) {
            const int sA = __shfl_sync(0xffffffffu, mysrc, j);
            const int sB = __shfl_sync(0xffffffffu, mysrc, j + 1);
            float wA = 0.0f, wB = 0.0f;
            if (lane < HEADS) {
                float eA = g_as[sA * HEADS + lane] + ad_l;
                float eB = g_as[sB * HEADS + lane] + ad_l;
                eA = eA > 0.0f ? eA : NEG_SLOPE * eA;
                eB = eB > 0.0f ? eB : NEG_SLOPE * eB;
                wA = __expf(eA);
                wB = __expf(eB);
                s += wA + wB;
            }
            const float wA0 = __shfl_sync(0xffffffffu, wA, 0 + hsel);
            const float wA1 = __shfl_sync(0xffffffffu, wA, 2 + hsel);
            const float wA2 = __shfl_sync(0xffffffffu, wA, 4 + hsel);
            const float wB0 = __shfl_sync(0xffffffffu, wB, 0 + hsel);
            const float wB1 = __shfl_sync(0xffffffffu, wB, 2 + hsel);
            const float wB2 = __shfl_sync(0xffffffffu, wB, 4 + hsel);
            const __half2* xA = (const __half2*)&g_xp_h[sA * HC];
            const __half2* xB = (const __half2*)&g_xp_h[sB * HC];
            float2 fA0 = __half22float2(xA[lane]);
            float2 fA1 = __half22float2(xA[32 + lane]);
            float2 fA2 = __half22float2(xA[64 + lane]);
            float2 fB0 = __half22float2(xB[lane]);
            float2 fB1 = __half22float2(xB[32 + lane]);
            float2 fB2 = __half22float2(xB[64 + lane]);
            A0.x += wA0 * fA0.x + wB0 * fB0.x;  A0.y += wA0 * fA0.y + wB0 * fB0.y;
            A1.x += wA1 * fA1.x + wB1 * fB1.x;  A1.y += wA1 * fA1.y + wB1 * fB1.y;
            A2.x += wA2 * fA2.x + wB2 * fB2.x;  A2.y += wA2 * fA2.y + wB2 * fB2.y;
        }
        if (j < nv) {
            const int sA = __shfl_sync(0xffffffffu, mysrc, j);
            float wA = 0.0f;
            if (lane < HEADS) {
                float eA = g_as[sA * HEADS + lane] + ad_l;
                eA = eA > 0.0f ? eA : NEG_SLOPE * eA;
                wA = __expf(eA);
                s += wA;
            }
            const float wA0 = __shfl_sync(0xffffffffu, wA, 0 + hsel);
            const float wA1 = __shfl_sync(0xffffffffu, wA, 2 + hsel);
            const float wA2 = __shfl_sync(0xffffffffu, wA, 4 + hsel);
            const __half2* xA = (const __half2*)&g_xp_h[sA * HC];
            float2 fA0 = __half22float2(xA[lane]);
            float2 fA1 = __half22float2(xA[32 + lane]);
            float2 fA2 = __half22float2(xA[64 + lane]);
            A0.x += wA0 * fA0.x;  A0.y += wA0 * fA0.y;
            A1.x += wA1 * fA1.x;  A1.y += wA1 * fA1.y;
            A2.x += wA2 * fA2.x;  A2.y += wA2 * fA2.y;
        }
    }

    const float s0 = __shfl_sync(0xffffffffu, s, 0 + hsel) + 1e-16f;
    const float s1 = __shfl_sync(0xffffffffu, s, 2 + hsel) + 1e-16f;
    const float s2 = __shfl_sync(0xffffffffu, s, 4 + hsel) + 1e-16f;

    float ox = A0.x / s0 + A1.x / s1 + A2.x / s2;
    float oy = A0.y / s0 + A1.y / s1 + A2.y / s2;
    ox += __shfl_xor_sync(0xffffffffu, ox, 16);
    oy += __shfl_xor_sync(0xffffffffu, oy, 16);

    if (lane < 16) {
        const int c0 = 2 * lane;
        float2 r;
        r.x = selu_f(ox * (1.0f / HEADS) + bias[c0]);
        r.y = selu_f(oy * (1.0f / HEADS) + bias[c0 + 1]);
        ((float2*)&out[d * OUT_F])[lane] = r;
    }
}

// ---------------- launch: fork edge pipeline / proj, join for agg ------------
static cudaStream_t s_edge = nullptr;
static cudaEvent_t  s_evFork = nullptr, s_evJoin = nullptr;

extern "C" void kernel_launch(void* const* d_in, const int* in_sizes, int n_in,
                              void* d_out, int out_size) {
    const float* x       = (const float*)d_in[0];
    const void*  ei      = d_in[1];
    const float* W       = (const float*)d_in[2];
    const float* att_src = (const float*)d_in[3];
    const float* att_dst = (const float*)d_in[4];
    const float* bias    = (const float*)d_in[5];
    float*       out     = (float*)d_out;

    if (s_edge == nullptr) {
        cudaStreamCreateWithFlags(&s_edge, cudaStreamNonBlocking);
        cudaEventCreateWithFlags(&s_evFork, cudaEventDisableTiming);
        cudaEventCreateWithFlags(&s_evJoin, cudaEventDisableTiming);
        cudaFuncSetAttribute(k_proj, cudaFuncAttributeMaxDynamicSharedMemorySize, SMEM_BYTES);
    }

    // fork: edge pipeline on s_edge, projection on the launch (capture) stream
    cudaEventRecord(s_evFork, 0);
    cudaStreamWaitEvent(s_edge, s_evFork, 0);

    k_hist  <<<(E_EDGES + 255) / 256, 256, 0, s_edge>>>(ei);   // idx 0
    k_scan1 <<<NB, SCAN_B, 0, s_edge>>>();                     // idx 1
    k_scan23<<<(N_NODES + 255) / 256, 256, 0, s_edge>>>();     // idx 2

    k_proj<<<PROJ_GRID, 256, SMEM_BYTES>>>(x, W, att_src, att_dst);  // idx 3 (profiled)

    k_scatter<<<(E_EDGES + 255) / 256, 256, 0, s_edge>>>(ei);  // idx 4
    cudaEventRecord(s_evJoin, s_edge);

    // join, then fused aggregate
    cudaStreamWaitEvent(0, s_evJoin, 0);
    k_agg<<<(N_NODES * 32 + 255) / 256, 256>>>(bias, out);     // idx 5
}

// round 15
// speedup vs baseline: 2.0267x; 2.0267x over previous
#include <cuda_runtime.h>
#include <cuda_fp16.h>
#include <mma.h>
#include <cstdint>
#include <math_constants.h>

using namespace nvcuda;

#define N_NODES 100000
#define E_EDGES 1600000
#define IN_F    128
#define OUT_F   32
#define HEADS   6
#define HC      (HEADS * OUT_F)   // 192
#define NEG_SLOPE 0.2f
#define SCAN_B  1024
#define NB      ((N_NODES + SCAN_B - 1) / SCAN_B)   // 98

// ---------------- scratch (device globals; no allocation allowed) ----------
__device__ __half g_xp_h[N_NODES * HC];    // projected features [N,H,C] (fp16)
__device__ float  g_as [N_NODES * HEADS];
__device__ float  g_ad [N_NODES * HEADS];
__device__ int    g_csr[E_EDGES];
__device__ int    g_deg[N_NODES];
__device__ int    g_row[N_NODES];
__device__ int    g_cur[N_NODES];
__device__ int    g_scan[NB * SCAN_B];
__device__ int    g_bsum[NB];
__device__ int    g_is64;

// ---------------- helpers ---------------------------------------------------
__device__ __forceinline__ float selu_f(float x) {
    const float scale = 1.0507009873554805f;
    const float alpha = 1.6732632423543772f;
    return x > 0.0f ? scale * x : scale * alpha * (expf(x) - 1.0f);
}

// ---------------- edge-stream prep: detect dtype + zero degrees --------------
__global__ void k_prep(const void* __restrict__ ei) {
    if (blockIdx.x == 0 && threadIdx.x == 0) {
        const long long* p = (const long long*)ei;
        int ok = 1;
        for (int i = 0; i < 16; i++) {
            long long v = p[i];
            if (v < 0 || v >= (long long)N_NODES) { ok = 0; break; }
        }
        g_is64 = ok;
    }
    int gid = blockIdx.x * blockDim.x + threadIdx.x;
    if (gid < N_NODES) g_deg[gid] = 0;
}

// ---------------- degree histogram (reads dst half of ei only) ---------------
__global__ void k_hist(const void* __restrict__ ei) {
    int i = blockIdx.x * blockDim.x + threadIdx.x;
    if (i >= E_EDGES) return;
    int d;
    if (g_is64) d = (int)((const long long*)ei)[E_EDGES + i];
    else        d = ((const int*)ei)[E_EDGES + i];
    atomicAdd(&g_deg[d], 1);
}

// ---------------- projection GEMM (tensor cores) -----------------------------
// Block: 256 threads (8 warps), 64-row x 192-col tile.  (R12-proven config)
#define PR 64
struct SmemGemm { __half xs[PR][136]; __half ws[32][200]; };
union SmemU { SmemGemm g; __half cs[PR][200]; };

__global__ __launch_bounds__(256) void k_proj(const float* __restrict__ x,
                                              const float* __restrict__ W,
                                              const float* __restrict__ att_src,
                                              const float* __restrict__ att_dst) {
    __shared__ SmemU su;
    const int t    = threadIdx.x;
    const int w    = t >> 5;
    const int lane = t & 31;
    const int rt   = w & 3;      // row tile (16 rows)
    const int ch   = w >> 2;     // col half (96 cols)
    const int row0 = blockIdx.x * PR;

    // load x tile -> fp16 smem (float2 -> half2), zero-pad OOB rows
#pragma unroll
    for (int q = 0; q < (PR * IN_F / 2) / 256; q++) {   // 16 iters
        int i  = t + 256 * q;
        int r  = i >> 6;            // 64 half2 per row
        int k2 = i & 63;
        int row = row0 + r;
        float2 f2 = (row < N_NODES) ? ((const float2*)x)[row * 64 + k2]
                                    : make_float2(0.0f, 0.0f);
        ((__half2*)&su.g.xs[r][0])[k2] = __floats2half2_rn(f2.x, f2.y);
    }

    wmma::fragment<wmma::accumulator, 16, 16, 16, float> acc[6];
#pragma unroll
    for (int j = 0; j < 6; j++) wmma::fill_fragment(acc[j], 0.0f);

    for (int kc = 0; kc < 4; kc++) {
        const int k0 = kc * 32;
        __syncthreads();
#pragma unroll
        for (int q = 0; q < (32 * HC / 2) / 256; q++) {  // 12 iters
            int i  = t + 256 * q;
            int kk = i / 96;
            int c2 = i - kk * 96;
            float2 f2 = ((const float2*)W)[(k0 + kk) * 96 + c2];
            ((__half2*)&su.g.ws[kk][0])[c2] = __floats2half2_rn(f2.x, f2.y);
        }
        __syncthreads();
#pragma unroll
        for (int ks = 0; ks < 2; ks++) {
            wmma::fragment<wmma::matrix_a, 16, 16, 16, __half, wmma::row_major> af;
            wmma::load_matrix_sync(af, &su.g.xs[rt * 16][k0 + ks * 16], 136);
#pragma unroll
            for (int j = 0; j < 6; j++) {
                wmma::fragment<wmma::matrix_b, 16, 16, 16, __half, wmma::row_major> bf;
                wmma::load_matrix_sync(bf, &su.g.ws[ks * 16][ch * 96 + j * 16], 200);
                wmma::mma_sync(acc[j], af, bf, acc[j]);
            }
        }
    }

    // stage C to smem as fp16
    __syncthreads();
#pragma unroll
    for (int j = 0; j < 6; j++) {
        wmma::fragment<wmma::accumulator, 16, 16, 16, __half> hf;
#pragma unroll
        for (int i = 0; i < hf.num_elements; i++) hf.x[i] = __float2half(acc[j].x[i]);
        wmma::store_matrix_sync(&su.cs[rt * 16][ch * 96 + j * 16], hf, 200, wmma::mem_row_major);
    }
    __syncthreads();

    // xp copy to global (uint4 = 8 halfs), coalesced
#pragma unroll
    for (int q = 0; q < (PR * HC / 8) / 256; q++) {   // 6 iters
        int i  = t + 256 * q;
        int r  = i / 24;
        int q8 = i - r * 24;
        int row = row0 + r;
        if (row < N_NODES) {
            uint4 v = *(const uint4*)&su.cs[r][q8 * 8];
            ((uint4*)&g_xp_h[row * HC])[q8] = v;
        }
    }

    // attention halves: warp w handles rows w*8 .. w*8+7
    float aS[6], aD[6];
#pragma unroll
    for (int g = 0; g < 6; g++) {
        aS[g] = att_src[g * OUT_F + lane];
        aD[g] = att_dst[g * OUT_F + lane];
    }
#pragma unroll
    for (int p = 0; p < 8; p++) {
        const int ri  = w * 8 + p;
        const int row = row0 + ri;
        if (row >= N_NODES) break;
#pragma unroll
        for (int g = 0; g < 6; g++) {
            float v = __half2float(su.cs[ri][g * OUT_F + lane]);
            float vs = v * aS[g];
            float vd = v * aD[g];
#pragma unroll
            for (int off = 16; off > 0; off >>= 1) {
                vs += __shfl_down_sync(0xffffffffu, vs, off);
                vd += __shfl_down_sync(0xffffffffu, vd, off);
            }
            if (lane == 0) {
                g_as[row * HEADS + g] = vs;
                g_ad[row * HEADS + g] = vd;
            }
        }
    }
}

// ---------------- scan (warp-shuffle version) --------------------------------
__global__ void k_scan1() {
    __shared__ int wsum[32];
    const int t = threadIdx.x, lane = t & 31, wid = t >> 5;
    const int i = blockIdx.x * SCAN_B + t;
    int v = (i < N_NODES) ? g_deg[i] : 0;
    int xv = v;
#pragma unroll
    for (int off = 1; off < 32; off <<= 1) {
        int y = __shfl_up_sync(0xffffffffu, xv, off);
        if (lane >= off) xv += y;
    }
    if (lane == 31) wsum[wid] = xv;
    __syncthreads();
    if (wid == 0) {
        int wv = wsum[lane];
#pragma unroll
        for (int off = 1; off < 32; off <<= 1) {
            int y = __shfl_up_sync(0xffffffffu, wv, off);
            if (lane >= off) wv += y;
        }
        wsum[lane] = wv;
    }
    __syncthreads();
    int incl = xv + (wid > 0 ? wsum[wid - 1] : 0);
    g_scan[blockIdx.x * SCAN_B + t] = incl;
    if (t == SCAN_B - 1) g_bsum[blockIdx.x] = incl;
}

__global__ void k_scan23() {
    __shared__ int sb[NB];
    int t = threadIdx.x;
    if (t < NB) sb[t] = g_bsum[t];
    __syncthreads();
    if (t == 0) {
        int run = 0;
        for (int b = 0; b < NB; b++) { int v = sb[b]; sb[b] = run; run += v; }
    }
    __syncthreads();
    int i = blockIdx.x * blockDim.x + t;
    if (i >= N_NODES) return;
    int rs = g_scan[i] - g_deg[i] + sb[i / SCAN_B];
    g_row[i] = rs;
    g_cur[i] = rs;
}

// ---------------- scatter: reads edge_index directly -------------------------
__global__ void k_scatter(const void* __restrict__ ei) {
    int i = blockIdx.x * blockDim.x + threadIdx.x;
    if (i >= E_EDGES) return;
    int s, d;
    if (g_is64) {
        const long long* p = (const long long*)ei;
        s = (int)p[i];
        d = (int)p[E_EDGES + i];
    } else {
        const int* p = (const int*)ei;
        s = p[i];
        d = p[E_EDGES + i];
    }
    int pos = atomicAdd(&g_cur[d], 1);
    g_csr[pos] = s;
}

// ---------------- fused softmax + aggregation + finalize ---------------------
// One warp per dst. half2 lane remap: lanes 0-15 even heads / 16-31 odd heads.
__global__ __launch_bounds__(256) void k_agg(const float* __restrict__ bias,
                                             float* __restrict__ out) {
    const int d    = (blockIdx.x * blockDim.x + threadIdx.x) >> 5;
    const int lane = threadIdx.x & 31;
    if (d >= N_NODES) return;

    const int base = g_row[d];
    const int deg  = g_deg[d];
    const int hsel = lane >> 4;          // 0: even heads, 1: odd heads

    float ad_l = 0.0f;
    if (lane < HEADS) ad_l = g_ad[d * HEADS + lane];

    float2 A0 = {0, 0}, A1 = {0, 0}, A2 = {0, 0};
    float s = 0.0f;

    for (int j0 = 0; j0 < deg; j0 += 32) {
        const int nv = min(32, deg - j0);
        int mysrc = 0;
        if (lane < nv) mysrc = g_csr[base + j0 + lane];

        int j = 0;
        for (; j + 1 < nv; j += 2) {
            const int sA = __shfl_sync(0xffffffffu, mysrc, j);
            const int sB = __shfl_sync(0xffffffffu, mysrc, j + 1);
            float wA = 0.0f, wB = 0.0f;
            if (lane < HEADS) {
                float eA = g_as[sA * HEADS + lane] + ad_l;
                float eB = g_as[sB * HEADS + lane] + ad_l;
                eA = eA > 0.0f ? eA : NEG_SLOPE * eA;
                eB = eB > 0.0f ? eB : NEG_SLOPE * eB;
                wA = __expf(eA);
                wB = __expf(eB);
                s += wA + wB;
            }
            const float wA0 = __shfl_sync(0xffffffffu, wA, 0 + hsel);
            const float wA1 = __shfl_sync(0xffffffffu, wA, 2 + hsel);
            const float wA2 = __shfl_sync(0xffffffffu, wA, 4 + hsel);
            const float wB0 = __shfl_sync(0xffffffffu, wB, 0 + hsel);
            const float wB1 = __shfl_sync(0xffffffffu, wB, 2 + hsel);
            const float wB2 = __shfl_sync(0xffffffffu, wB, 4 + hsel);
            const __half2* xA = (const __half2*)&g_xp_h[sA * HC];
            const __half2* xB = (const __half2*)&g_xp_h[sB * HC];
            float2 fA0 = __half22float2(xA[lane]);
            float2 fA1 = __half22float2(xA[32 + lane]);
            float2 fA2 = __half22float2(xA[64 + lane]);
            float2 fB0 = __half22float2(xB[lane]);
            float2 fB1 = __half22float2(xB[32 + lane]);
            float2 fB2 = __half22float2(xB[64 + lane]);
            A0.x += wA0 * fA0.x + wB0 * fB0.x;  A0.y += wA0 * fA0.y + wB0 * fB0.y;
            A1.x += wA1 * fA1.x + wB1 * fB1.x;  A1.y += wA1 * fA1.y + wB1 * fB1.y;
            A2.x += wA2 * fA2.x + wB2 * fB2.x;  A2.y += wA2 * fA2.y + wB2 * fB2.y;
        }
        if (j < nv) {
            const int sA = __shfl_sync(0xffffffffu, mysrc, j);
            float wA = 0.0f;
            if (lane < HEADS) {
                float eA = g_as[sA * HEADS + lane] + ad_l;
                eA = eA > 0.0f ? eA : NEG_SLOPE * eA;
                wA = __expf(eA);
                s += wA;
            }
            const float wA0 = __shfl_sync(0xffffffffu, wA, 0 + hsel);
            const float wA1 = __shfl_sync(0xffffffffu, wA, 2 + hsel);
            const float wA2 = __shfl_sync(0xffffffffu, wA, 4 + hsel);
            const __half2* xA = (const __half2*)&g_xp_h[sA * HC];
            float2 fA0 = __half22float2(xA[lane]);
            float2 fA1 = __half22float2(xA[32 + lane]);
            float2 fA2 = __half22float2(xA[64 + lane]);
            A0.x += wA0 * fA0.x;  A0.y += wA0 * fA0.y;
            A1.x += wA1 * fA1.x;  A1.y += wA1 * fA1.y;
            A2.x += wA2 * fA2.x;  A2.y += wA2 * fA2.y;
        }
    }

    const float s0 = __shfl_sync(0xffffffffu, s, 0 + hsel) + 1e-16f;
    const float s1 = __shfl_sync(0xffffffffu, s, 2 + hsel) + 1e-16f;
    const float s2 = __shfl_sync(0xffffffffu, s, 4 + hsel) + 1e-16f;

    float ox = A0.x / s0 + A1.x / s1 + A2.x / s2;
    float oy = A0.y / s0 + A1.y / s1 + A2.y / s2;
    ox += __shfl_xor_sync(0xffffffffu, ox, 16);
    oy += __shfl_xor_sync(0xffffffffu, oy, 16);

    if (lane < 16) {
        const int c0 = 2 * lane;
        float2 r;
        r.x = selu_f(ox * (1.0f / HEADS) + bias[c0]);
        r.y = selu_f(oy * (1.0f / HEADS) + bias[c0 + 1]);
        ((float2*)&out[d * OUT_F])[lane] = r;
    }
}

// ---------------- launch: fork edge pipeline / proj, join for agg ------------
// Edge stream gets elevated priority: its chain is the longer fork arm, so it
// should win SM allocation during the overlap window.
static cudaStream_t s_edge = nullptr;
static cudaEvent_t  s_evFork = nullptr, s_evJoin = nullptr;

extern "C" void kernel_launch(void* const* d_in, const int* in_sizes, int n_in,
                              void* d_out, int out_size) {
    const float* x       = (const float*)d_in[0];
    const void*  ei      = d_in[1];
    const float* W       = (const float*)d_in[2];
    const float* att_src = (const float*)d_in[3];
    const float* att_dst = (const float*)d_in[4];
    const float* bias    = (const float*)d_in[5];
    float*       out     = (float*)d_out;

    if (s_edge == nullptr) {
        int loPri = 0, hiPri = 0;
        cudaDeviceGetStreamPriorityRange(&loPri, &hiPri);
        cudaStreamCreateWithPriority(&s_edge, cudaStreamNonBlocking, hiPri);
        cudaEventCreateWithFlags(&s_evFork, cudaEventDisableTiming);
        cudaEventCreateWithFlags(&s_evJoin, cudaEventDisableTiming);
    }

    // fork: edge pipeline on s_edge, projection on the launch (capture) stream
    cudaEventRecord(s_evFork, 0);
    cudaStreamWaitEvent(s_edge, s_evFork, 0);

    k_prep  <<<(N_NODES + 255) / 256, 256, 0, s_edge>>>(ei);   // idx 0
    k_hist  <<<(E_EDGES + 255) / 256, 256, 0, s_edge>>>(ei);   // idx 1
    k_scan1 <<<NB, SCAN_B, 0, s_edge>>>();                     // idx 2

    k_proj<<<(N_NODES + PR - 1) / PR, 256>>>(x, W, att_src, att_dst);  // idx 3 (profiled)

    k_scan23 <<<(N_NODES + 255) / 256, 256, 0, s_edge>>>();    // idx 4
    k_scatter<<<(E_EDGES + 255) / 256, 256, 0, s_edge>>>(ei);  // idx 5
    cudaEventRecord(s_evJoin, s_edge);

    // join, then fused aggregate
    cudaStreamWaitEvent(0, s_evJoin, 0);
    k_agg<<<(N_NODES * 32 + 255) / 256, 256>>>(bias, out);     // idx 6
}

// round 17
// speedup vs baseline: 2.0666x; 1.0197x over previous
#include <cuda_runtime.h>
#include <cuda_fp16.h>
#include <mma.h>
#include <cstdint>
#include <math_constants.h>

using namespace nvcuda;

#define N_NODES 100000
#define E_EDGES 1600000
#define IN_F    128
#define OUT_F   32
#define HEADS   6
#define HC      (HEADS * OUT_F)   // 192
#define NEG_SLOPE 0.2f
#define SCAN_B  1024
#define NB      ((N_NODES + SCAN_B - 1) / SCAN_B)   // 98

// ---------------- scratch (device globals; no allocation allowed) ----------
__device__ __half g_xp_h[N_NODES * HC];    // projected features [N,H,C] (fp16)
__device__ float  g_as [N_NODES * HEADS];
__device__ float  g_ad [N_NODES * HEADS];
__device__ int    g_csr[E_EDGES];
__device__ int    g_deg[N_NODES];
__device__ int    g_row[N_NODES];
__device__ int    g_cur[N_NODES];
__device__ int    g_scan[NB * SCAN_B];
__device__ int    g_bsum[NB];
__device__ int    g_is64;

// ---------------- helpers ---------------------------------------------------
__device__ __forceinline__ float selu_f(float x) {
    const float scale = 1.0507009873554805f;
    const float alpha = 1.6732632423543772f;
    return x > 0.0f ? scale * x : scale * alpha * (expf(x) - 1.0f);
}

// ---------------- edge-stream prep: detect dtype + zero degrees --------------
__global__ void k_prep(const void* __restrict__ ei) {
    if (blockIdx.x == 0 && threadIdx.x == 0) {
        const long long* p = (const long long*)ei;
        int ok = 1;
        for (int i = 0; i < 16; i++) {
            long long v = p[i];
            if (v < 0 || v >= (long long)N_NODES) { ok = 0; break; }
        }
        g_is64 = ok;
    }
    int gid = blockIdx.x * blockDim.x + threadIdx.x;
    if (gid < N_NODES) g_deg[gid] = 0;
}

// ---------------- degree histogram (reads dst half of ei only) ---------------
__global__ void k_hist(const void* __restrict__ ei) {
    int i = blockIdx.x * blockDim.x + threadIdx.x;
    if (i >= E_EDGES) return;
    int d;
    if (g_is64) d = (int)((const long long*)ei)[E_EDGES + i];
    else        d = ((const int*)ei)[E_EDGES + i];
    atomicAdd(&g_deg[d], 1);
}

// ---------------- projection GEMM (tensor cores) -----------------------------
// Block: 256 threads (8 warps), 64-row x 192-col tile.  (R12-proven config)
#define PR 64
struct SmemGemm { __half xs[PR][136]; __half ws[32][200]; };
union SmemU { SmemGemm g; __half cs[PR][200]; };

__global__ __launch_bounds__(256) void k_proj(const float* __restrict__ x,
                                              const float* __restrict__ W,
                                              const float* __restrict__ att_src,
                                              const float* __restrict__ att_dst) {
    __shared__ SmemU su;
    const int t    = threadIdx.x;
    const int w    = t >> 5;
    const int lane = t & 31;
    const int rt   = w & 3;      // row tile (16 rows)
    const int ch   = w >> 2;     // col half (96 cols)
    const int row0 = blockIdx.x * PR;

    // load x tile -> fp16 smem (float2 -> half2), zero-pad OOB rows
#pragma unroll
    for (int q = 0; q < (PR * IN_F / 2) / 256; q++) {   // 16 iters
        int i  = t + 256 * q;
        int r  = i >> 6;            // 64 half2 per row
        int k2 = i & 63;
        int row = row0 + r;
        float2 f2 = (row < N_NODES) ? ((const float2*)x)[row * 64 + k2]
                                    : make_float2(0.0f, 0.0f);
        ((__half2*)&su.g.xs[r][0])[k2] = __floats2half2_rn(f2.x, f2.y);
    }

    wmma::fragment<wmma::accumulator, 16, 16, 16, float> acc[6];
#pragma unroll
    for (int j = 0; j < 6; j++) wmma::fill_fragment(acc[j], 0.0f);

    for (int kc = 0; kc < 4; kc++) {
        const int k0 = kc * 32;
        __syncthreads();
#pragma unroll
        for (int q = 0; q < (32 * HC / 2) / 256; q++) {  // 12 iters
            int i  = t + 256 * q;
            int kk = i / 96;
            int c2 = i - kk * 96;
            float2 f2 = ((const float2*)W)[(k0 + kk) * 96 + c2];
            ((__half2*)&su.g.ws[kk][0])[c2] = __floats2half2_rn(f2.x, f2.y);
        }
        __syncthreads();
#pragma unroll
        for (int ks = 0; ks < 2; ks++) {
            wmma::fragment<wmma::matrix_a, 16, 16, 16, __half, wmma::row_major> af;
            wmma::load_matrix_sync(af, &su.g.xs[rt * 16][k0 + ks * 16], 136);
#pragma unroll
            for (int j = 0; j < 6; j++) {
                wmma::fragment<wmma::matrix_b, 16, 16, 16, __half, wmma::row_major> bf;
                wmma::load_matrix_sync(bf, &su.g.ws[ks * 16][ch * 96 + j * 16], 200);
                wmma::mma_sync(acc[j], af, bf, acc[j]);
            }
        }
    }

    // stage C to smem as fp16
    __syncthreads();
#pragma unroll
    for (int j = 0; j < 6; j++) {
        wmma::fragment<wmma::accumulator, 16, 16, 16, __half> hf;
#pragma unroll
        for (int i = 0; i < hf.num_elements; i++) hf.x[i] = __float2half(acc[j].x[i]);
        wmma::store_matrix_sync(&su.cs[rt * 16][ch * 96 + j * 16], hf, 200, wmma::mem_row_major);
    }
    __syncthreads();

    // xp copy to global (uint4 = 8 halfs), coalesced
#pragma unroll
    for (int q = 0; q < (PR * HC / 8) / 256; q++) {   // 6 iters
        int i  = t + 256 * q;
        int r  = i / 24;
        int q8 = i - r * 24;
        int row = row0 + r;
        if (row < N_NODES) {
            uint4 v = *(const uint4*)&su.cs[r][q8 * 8];
            ((uint4*)&g_xp_h[row * HC])[q8] = v;
        }
    }

    // attention halves: warp w handles rows w*8 .. w*8+7
    float aS[6], aD[6];
#pragma unroll
    for (int g = 0; g < 6; g++) {
        aS[g] = att_src[g * OUT_F + lane];
        aD[g] = att_dst[g * OUT_F + lane];
    }
#pragma unroll
    for (int p = 0; p < 8; p++) {
        const int ri  = w * 8 + p;
        const int row = row0 + ri;
        if (row >= N_NODES) break;
#pragma unroll
        for (int g = 0; g < 6; g++) {
            float v = __half2float(su.cs[ri][g * OUT_F + lane]);
            float vs = v * aS[g];
            float vd = v * aD[g];
#pragma unroll
            for (int off = 16; off > 0; off >>= 1) {
                vs += __shfl_down_sync(0xffffffffu, vs, off);
                vd += __shfl_down_sync(0xffffffffu, vd, off);
            }
            if (lane == 0) {
                g_as[row * HEADS + g] = vs;
                g_ad[row * HEADS + g] = vd;
            }
        }
    }
}

// ---------------- scan (warp-shuffle version) --------------------------------
__global__ void k_scan1() {
    __shared__ int wsum[32];
    const int t = threadIdx.x, lane = t & 31, wid = t >> 5;
    const int i = blockIdx.x * SCAN_B + t;
    int v = (i < N_NODES) ? g_deg[i] : 0;
    int xv = v;
#pragma unroll
    for (int off = 1; off < 32; off <<= 1) {
        int y = __shfl_up_sync(0xffffffffu, xv, off);
        if (lane >= off) xv += y;
    }
    if (lane == 31) wsum[wid] = xv;
    __syncthreads();
    if (wid == 0) {
        int wv = wsum[lane];
#pragma unroll
        for (int off = 1; off < 32; off <<= 1) {
            int y = __shfl_up_sync(0xffffffffu, wv, off);
            if (lane >= off) wv += y;
        }
        wsum[lane] = wv;
    }
    __syncthreads();
    int incl = xv + (wid > 0 ? wsum[wid - 1] : 0);
    g_scan[blockIdx.x * SCAN_B + t] = incl;
    if (t == SCAN_B - 1) g_bsum[blockIdx.x] = incl;
}

__global__ void k_scan23() {
    __shared__ int sb[NB];
    int t = threadIdx.x;
    if (t < NB) sb[t] = g_bsum[t];
    __syncthreads();
    if (t == 0) {
        int run = 0;
        for (int b = 0; b < NB; b++) { int v = sb[b]; sb[b] = run; run += v; }
    }
    __syncthreads();
    int i = blockIdx.x * blockDim.x + t;
    if (i >= N_NODES) return;
    int rs = g_scan[i] - g_deg[i] + sb[i / SCAN_B];
    g_row[i] = rs;
    g_cur[i] = rs;
}

// ---------------- scatter: reads edge_index directly -------------------------
__global__ void k_scatter(const void* __restrict__ ei) {
    int i = blockIdx.x * blockDim.x + threadIdx.x;
    if (i >= E_EDGES) return;
    int s, d;
    if (g_is64) {
        const long long* p = (const long long*)ei;
        s = (int)p[i];
        d = (int)p[E_EDGES + i];
    } else {
        const int* p = (const int*)ei;
        s = p[i];
        d = p[E_EDGES + i];
    }
    int pos = atomicAdd(&g_cur[d], 1);
    g_csr[pos] = s;
}

// ---------------- fused softmax + aggregation + finalize ---------------------
// One warp per dst; half2 lane remap (lanes 0-15 even heads / 16-31 odd heads).
// 4-edge software pipeline: 4 logit gathers + 4 exps, 12 weight shfls, then 12
// independent feature loads in flight before any FMA (hides L2 latency).
__global__ __launch_bounds__(256) void k_agg(const float* __restrict__ bias,
                                             float* __restrict__ out) {
    const int d    = (blockIdx.x * blockDim.x + threadIdx.x) >> 5;
    const int lane = threadIdx.x & 31;
    if (d >= N_NODES) return;

    const int base = g_row[d];
    const int deg  = g_deg[d];
    const int hsel = lane >> 4;          // 0: even heads, 1: odd heads

    float ad_l = 0.0f;
    if (lane < HEADS) ad_l = g_ad[d * HEADS + lane];

    float2 A0 = {0, 0}, A1 = {0, 0}, A2 = {0, 0};
    float s = 0.0f;

    for (int j0 = 0; j0 < deg; j0 += 32) {
        const int nv = min(32, deg - j0);
        int mysrc = 0;
        if (lane < nv) mysrc = g_csr[base + j0 + lane];

        int j = 0;
        for (; j + 3 < nv; j += 4) {
            const int sA = __shfl_sync(0xffffffffu, mysrc, j);
            const int sB = __shfl_sync(0xffffffffu, mysrc, j + 1);
            const int sC = __shfl_sync(0xffffffffu, mysrc, j + 2);
            const int sD = __shfl_sync(0xffffffffu, mysrc, j + 3);

            float wA = 0.0f, wB = 0.0f, wC = 0.0f, wD = 0.0f;
            if (lane < HEADS) {
                float eA = g_as[sA * HEADS + lane] + ad_l;
                float eB = g_as[sB * HEADS + lane] + ad_l;
                float eC = g_as[sC * HEADS + lane] + ad_l;
                float eD = g_as[sD * HEADS + lane] + ad_l;
                eA = eA > 0.0f ? eA : NEG_SLOPE * eA;
                eB = eB > 0.0f ? eB : NEG_SLOPE * eB;
                eC = eC > 0.0f ? eC : NEG_SLOPE * eC;
                eD = eD > 0.0f ? eD : NEG_SLOPE * eD;
                wA = __expf(eA);
                wB = __expf(eB);
                wC = __expf(eC);
                wD = __expf(eD);
                s += (wA + wB) + (wC + wD);
            }
            const float wA0 = __shfl_sync(0xffffffffu, wA, 0 + hsel);
            const float wA1 = __shfl_sync(0xffffffffu, wA, 2 + hsel);
            const float wA2 = __shfl_sync(0xffffffffu, wA, 4 + hsel);
            const float wB0 = __shfl_sync(0xffffffffu, wB, 0 + hsel);
            const float wB1 = __shfl_sync(0xffffffffu, wB, 2 + hsel);
            const float wB2 = __shfl_sync(0xffffffffu, wB, 4 + hsel);
            const float wC0 = __shfl_sync(0xffffffffu, wC, 0 + hsel);
            const float wC1 = __shfl_sync(0xffffffffu, wC, 2 + hsel);
            const float wC2 = __shfl_sync(0xffffffffu, wC, 4 + hsel);
            const float wD0 = __shfl_sync(0xffffffffu, wD, 0 + hsel);
            const float wD1 = __shfl_sync(0xffffffffu, wD, 2 + hsel);
            const float wD2 = __shfl_sync(0xffffffffu, wD, 4 + hsel);

            const __half2* xA = (const __half2*)&g_xp_h[sA * HC];
            const __half2* xB = (const __half2*)&g_xp_h[sB * HC];
            const __half2* xC = (const __half2*)&g_xp_h[sC * HC];
            const __half2* xD = (const __half2*)&g_xp_h[sD * HC];
            // issue all 12 loads before consuming (compiler keeps them in flight)
            const __half2 hA0 = xA[lane],      hB0 = xB[lane],      hC0 = xC[lane],      hD0 = xD[lane];
            const __half2 hA1 = xA[32 + lane], hB1 = xB[32 + lane], hC1 = xC[32 + lane], hD1 = xD[32 + lane];
            const __half2 hA2 = xA[64 + lane], hB2 = xB[64 + lane], hC2 = xC[64 + lane], hD2 = xD[64 + lane];

            float2 f;
            f = __half22float2(hA0); A0.x += wA0 * f.x; A0.y += wA0 * f.y;
            f = __half22float2(hB0); A0.x += wB0 * f.x; A0.y += wB0 * f.y;
            f = __half22float2(hC0); A0.x += wC0 * f.x; A0.y += wC0 * f.y;
            f = __half22float2(hD0); A0.x += wD0 * f.x; A0.y += wD0 * f.y;
            f = __half22float2(hA1); A1.x += wA1 * f.x; A1.y += wA1 * f.y;
            f = __half22float2(hB1); A1.x += wB1 * f.x; A1.y += wB1 * f.y;
            f = __half22float2(hC1); A1.x += wC1 * f.x; A1.y += wC1 * f.y;
            f = __half22float2(hD1); A1.x += wD1 * f.x; A1.y += wD1 * f.y;
            f = __half22float2(hA2); A2.x += wA2 * f.x; A2.y += wA2 * f.y;
            f = __half22float2(hB2); A2.x += wB2 * f.x; A2.y += wB2 * f.y;
            f = __half22float2(hC2); A2.x += wC2 * f.x; A2.y += wC2 * f.y;
            f = __half22float2(hD2); A2.x += wD2 * f.x; A2.y += wD2 * f.y;
        }
        for (; j < nv; j++) {
            const int sA = __shfl_sync(0xffffffffu, mysrc, j);
            float wA = 0.0f;
            if (lane < HEADS) {
                float eA = g_as[sA * HEADS + lane] + ad_l;
                eA = eA > 0.0f ? eA : NEG_SLOPE * eA;
                wA = __expf(eA);
                s += wA;
            }
            const float wA0 = __shfl_sync(0xffffffffu, wA, 0 + hsel);
            const float wA1 = __shfl_sync(0xffffffffu, wA, 2 + hsel);
            const float wA2 = __shfl_sync(0xffffffffu, wA, 4 + hsel);
            const __half2* xA = (const __half2*)&g_xp_h[sA * HC];
            float2 fA0 = __half22float2(xA[lane]);
            float2 fA1 = __half22float2(xA[32 + lane]);
            float2 fA2 = __half22float2(xA[64 + lane]);
            A0.x += wA0 * fA0.x;  A0.y += wA0 * fA0.y;
            A1.x += wA1 * fA1.x;  A1.y += wA1 * fA1.y;
            A2.x += wA2 * fA2.x;  A2.y += wA2 * fA2.y;
        }
    }

    const float s0 = __shfl_sync(0xffffffffu, s, 0 + hsel) + 1e-16f;
    const float s1 = __shfl_sync(0xffffffffu, s, 2 + hsel) + 1e-16f;
    const float s2 = __shfl_sync(0xffffffffu, s, 4 + hsel) + 1e-16f;

    float ox = A0.x / s0 + A1.x / s1 + A2.x / s2;
    float oy = A0.y / s0 + A1.y / s1 + A2.y / s2;
    ox += __shfl_xor_sync(0xffffffffu, ox, 16);
    oy += __shfl_xor_sync(0xffffffffu, oy, 16);

    if (lane < 16) {
        const int c0 = 2 * lane;
        float2 r;
        r.x = selu_f(ox * (1.0f / HEADS) + bias[c0]);
        r.y = selu_f(oy * (1.0f / HEADS) + bias[c0 + 1]);
        ((float2*)&out[d * OUT_F])[lane] = r;
    }
}

// ---------------- launch: fork edge pipeline / proj, join for agg ------------
static cudaStream_t s_edge = nullptr;
static cudaEvent_t  s_evFork = nullptr, s_evJoin = nullptr;

extern "C" void kernel_launch(void* const* d_in, const int* in_sizes, int n_in,
                              void* d_out, int out_size) {
    const float* x       = (const float*)d_in[0];
    const void*  ei      = d_in[1];
    const float* W       = (const float*)d_in[2];
    const float* att_src = (const float*)d_in[3];
    const float* att_dst = (const float*)d_in[4];
    const float* bias    = (const float*)d_in[5];
    float*       out     = (float*)d_out;

    if (s_edge == nullptr) {
        int loPri = 0, hiPri = 0;
        cudaDeviceGetStreamPriorityRange(&loPri, &hiPri);
        cudaStreamCreateWithPriority(&s_edge, cudaStreamNonBlocking, hiPri);
        cudaEventCreateWithFlags(&s_evFork, cudaEventDisableTiming);
        cudaEventCreateWithFlags(&s_evJoin, cudaEventDisableTiming);
    }

    // fork: edge pipeline on s_edge, projection on the launch (capture) stream
    cudaEventRecord(s_evFork, 0);
    cudaStreamWaitEvent(s_edge, s_evFork, 0);

    k_prep  <<<(N_NODES + 255) / 256, 256, 0, s_edge>>>(ei);   // idx 0
    k_hist  <<<(E_EDGES + 255) / 256, 256, 0, s_edge>>>(ei);   // idx 1
    k_scan1 <<<NB, SCAN_B, 0, s_edge>>>();                     // idx 2

    k_proj<<<(N_NODES + PR - 1) / PR, 256>>>(x, W, att_src, att_dst);  // idx 3 (profiled)

    k_scan23 <<<(N_NODES + 255) / 256, 256, 0, s_edge>>>();    // idx 4
    k_scatter<<<(E_EDGES + 255) / 256, 256, 0, s_edge>>>(ei);  // idx 5
    cudaEventRecord(s_evJoin, s_edge);

    // join, then fused aggregate
    cudaStreamWaitEvent(0, s_evJoin, 0);
    k_agg<<<(N_NODES * 32 + 255) / 256, 256>>>(bias, out);     // idx 6
}